// round 15
// baseline (speedup 1.0000x reference)
#include <cuda_runtime.h>
#include <cuda_bf16.h>

typedef unsigned long long ull;

// scratch (device globals; allocations are forbidden)
__device__ ull g_k[64 * 64];                     // paired circ-conv kernels [cpair][8*8]
__device__ ull g_t[(size_t)8 * 32 * 256 * 256];  // paired intermediate [b][cpair][256][256]

__device__ __forceinline__ ull pk2(float a, float b) {
    ull r; asm("mov.b64 %0, {%1, %2};" : "=l"(r) : "f"(a), "f"(b)); return r;
}
__device__ __forceinline__ void fma2(ull &d, ull a, ull b) {
    asm("fma.rn.f32x2 %0, %1, %2, %0;" : "+l"(d) : "l"(a), "l"(b));
}
__device__ __forceinline__ float lo32(ull v) { return __int_as_float((int)(v & 0xffffffffull)); }
__device__ __forceinline__ float hi32(ull v) { return __int_as_float((int)(v >> 32)); }

// ---- kernel 1: build paired circular-conv kernels from fft_filt -------------
__global__ void k_build(const float* __restrict__ filt) {
    int cp = blockIdx.x, pix = threadIdx.x;
    int di = pix >> 3, dj = pix & 7;
    float v[2];
#pragma unroll
    for (int h = 0; h < 2; h++) {
        const float* F = filt + (cp * 2 + h) * 40;
        float s = 0.f;
        for (int ky = 0; ky < 8; ky++)
            for (int kx = 0; kx < 5; kx++) {
                float w = (kx == 0 || kx == 4) ? 1.f : 2.f;
                int m = (ky * di + kx * dj) & 7;
                s += w * F[ky * 5 + kx] * cospif(0.25f * (float)m);
            }
        v[h] = s * (1.f / 64.f);
    }
    g_k[cp * 64 + pix] = pk2(v[0], v[1]);
}

// ---- kernel 2: passA, 512 threads, 2 patches per iteration ------------------
// smem: sWin(paired)64K | sWb(paired)16K | bufA 68K | bufB 68K  = 221184 B
// bufA: x [128c][132f]  -> g [64c][132f] + t [32cp][130ull]
// bufB: y [64cp][130ull] -> z in place
__global__ __launch_bounds__(512, 1) void passA(const float* __restrict__ x,
                                                const float* __restrict__ w_in,
                                                const float* __restrict__ w_before) {
    extern __shared__ char sm[];
    ull*  sWin = (ull*)sm;                // [128k][64op]
    ull*  sWb  = (ull*)(sm + 65536);      // [64k][32op]
    char* bufA = sm + 81920;              // 69632 B
    char* bufB = sm + 151552;             // 69632 B
    int tid = threadIdx.x;

    // stage + pack weights (paired u64)
    {
        float* stA = (float*)bufA;
        float* stB = (float*)bufB;
        for (int i = tid; i < 16384; i += 512) stA[i] = w_in[i];
        for (int i = tid; i < 4096;  i += 512) stB[i] = w_before[i];
        __syncthreads();
        for (int i = tid; i < 8192; i += 512) {
            int k = i >> 6, op = i & 63;
            sWin[k * 64 + op] = pk2(stA[(2 * op) * 128 + k], stA[(2 * op + 1) * 128 + k]);
        }
        for (int i = tid; i < 2048; i += 512) {
            int k = i >> 5, op = i & 31;
            sWb[k * 32 + op] = pk2(stB[(2 * op) * 64 + k], stB[(2 * op + 1) * 64 + k]);
        }
        __syncthreads();
    }

    const int og  = tid & 15, pg  = tid >> 4;  // GEMM1: 4 opairs x 4 px, pg 0..31
    const int cc  = tid >> 3, sub = tid & 7;   // circconv: cp 0..63, ii=sub, 2 patches
    const int og2 = tid & 7,  pg2 = tid >> 3;  // GEMM2: 4 opairs x 2 px, pg2 0..63

    for (int q = 0; q < 4; ++q) {
        int p2 = blockIdx.x * 4 + q;                       // 0..4095 patch pairs
        int b = p2 >> 9, rem = p2 & 511;
        int ph = rem >> 4, pw0 = (rem & 15) << 1;
        const float* xb = x + ((long)b << 23) + (ph << 11) + (pw0 << 3);

        // load x: [128c][132f] in bufA, px = pc*64 + i*8 + j
        {
            float* sX = (float*)bufA;
            for (int f = tid; f < 4096; f += 512) {
                int c = f >> 5, r = f & 31, i = r >> 2, qq = r & 3;
                float4 v = *(const float4*)(xb + ((long)c << 16) + (i << 8) + (qq << 2));
                int px = (qq < 2) ? (i * 8 + qq * 4) : (64 + i * 8 + (qq - 2) * 4);
                *(float4*)(sX + c * 132 + px) = v;
            }
        }
        __syncthreads();

        // GEMM1: y[64op][128px] paired -> bufB
        {
            const float* sX = (const float*)bufA;
            ull acc[4][4];
#pragma unroll
            for (int i = 0; i < 4; i++)
#pragma unroll
                for (int j = 0; j < 4; j++) acc[i][j] = 0ull;
#pragma unroll 4
            for (int k = 0; k < 128; k++) {
                const ull* Ar = sWin + k * 64 + og;
                ull A0 = Ar[0], A1 = Ar[16], A2 = Ar[32], A3 = Ar[48];
                float4 b0 = *(const float4*)(sX + k * 132 + pg * 4);
                ull B[4] = {pk2(b0.x, b0.x), pk2(b0.y, b0.y), pk2(b0.z, b0.z), pk2(b0.w, b0.w)};
#pragma unroll
                for (int j = 0; j < 4; j++) {
                    fma2(acc[0][j], A0, B[j]); fma2(acc[1][j], A1, B[j]);
                    fma2(acc[2][j], A2, B[j]); fma2(acc[3][j], A3, B[j]);
                }
            }
            ull* sY = (ull*)bufB;
#pragma unroll
            for (int i = 0; i < 4; i++) {
                ull* dst = sY + (og + 16 * i) * 130 + pg * 4;
                ulonglong2 v0; v0.x = acc[i][0]; v0.y = acc[i][1];
                ulonglong2 v1; v1.x = acc[i][2]; v1.y = acc[i][3];
                *(ulonglong2*)(dst)     = v0;
                *(ulonglong2*)(dst + 2) = v1;
            }
        }
        __syncthreads();

        // circular conv 8x8 (K from global L2): z overwrites y in bufB
        {
            ull* sY = (ull*)bufB;
            const ull* kbase = g_k + cc * 64;
            ull z0[8], z1[8];
#pragma unroll
            for (int j = 0; j < 8; j++) { z0[j] = 0; z1[j] = 0; }
#pragma unroll 2
            for (int a = 0; a < 8; a++) {
                const ull* yr = sY + cc * 130 + a * 8;
                ull ya[8], yb[8];
#pragma unroll
                for (int j = 0; j < 8; j += 2) {
                    ulonglong2 v0 = *(const ulonglong2*)(yr + j);      ya[j] = v0.x; ya[j + 1] = v0.y;
                    ulonglong2 v1 = *(const ulonglong2*)(yr + 64 + j); yb[j] = v1.x; yb[j + 1] = v1.y;
                }
                int r1 = (sub - a) & 7;
                ull k1[8];
#pragma unroll
                for (int j = 0; j < 8; j += 2) {
                    ulonglong2 u1 = *(const ulonglong2*)(kbase + r1 * 8 + j);
                    k1[j] = u1.x; k1[j + 1] = u1.y;
                }
#pragma unroll
                for (int j = 0; j < 8; j++)
#pragma unroll
                    for (int bb = 0; bb < 8; bb++) {
                        int r = (j - bb) & 7;
                        fma2(z0[j], ya[bb], k1[r]);
                        fma2(z1[j], yb[bb], k1[r]);
                    }
            }
            __syncwarp();  // all readers of this cc's rows are in this warp
            ull* zr = sY + cc * 130 + sub * 8;
#pragma unroll
            for (int j = 0; j < 8; j += 2) {
                ulonglong2 v;
                v.x = z0[j]; v.y = z0[j + 1]; *(ulonglong2*)(zr + j) = v;
                v.x = z1[j]; v.y = z1[j + 1]; *(ulonglong2*)(zr + 64 + j) = v;
            }
        }
        __syncthreads();

        // exact GELU gate: g floats [64ch][132] -> bufA
        {
            const ull* sZ = (const ull*)bufB;
            float* sG = (float*)bufA;
            for (int idx = tid; idx < 4096; idx += 512) {
                int cp = idx >> 7, u = idx & 127;
                ull za = sZ[cp * 130 + u], zb = sZ[(cp + 32) * 130 + u];
                float a0 = lo32(za), a1 = hi32(za);
                sG[(2 * cp) * 132 + u] =
                    0.5f * a0 * (1.f + erff(a0 * 0.70710678118654752f)) * lo32(zb);
                sG[(2 * cp + 1) * 132 + u] =
                    0.5f * a1 * (1.f + erff(a1 * 0.70710678118654752f)) * hi32(zb);
            }
        }
        __syncthreads();

        // GEMM2: t[32op][128px] paired -> bufA+33792 (all 512 threads)
        {
            const float* sG = (const float*)bufA;
            ull acc[4][2];
#pragma unroll
            for (int i = 0; i < 4; i++) { acc[i][0] = 0ull; acc[i][1] = 0ull; }
#pragma unroll 4
            for (int k = 0; k < 64; k++) {
                const ull* Ar = sWb + k * 32 + og2;
                ull A0 = Ar[0], A1 = Ar[8], A2 = Ar[16], A3 = Ar[24];
                float2 gg = *(const float2*)(sG + k * 132 + pg2 * 2);
                ull b0 = pk2(gg.x, gg.x), b1 = pk2(gg.y, gg.y);
                fma2(acc[0][0], A0, b0); fma2(acc[0][1], A0, b1);
                fma2(acc[1][0], A1, b0); fma2(acc[1][1], A1, b1);
                fma2(acc[2][0], A2, b0); fma2(acc[2][1], A2, b1);
                fma2(acc[3][0], A3, b0); fma2(acc[3][1], A3, b1);
            }
            ull* sT = (ull*)(bufA + 33792);
#pragma unroll
            for (int i = 0; i < 4; i++) {
                ulonglong2 v; v.x = acc[i][0]; v.y = acc[i][1];
                *(ulonglong2*)(sT + (og2 + 8 * i) * 130 + pg2 * 2) = v;
            }
        }
        __syncthreads();

        // store paired t to global (128B-contiguous across the 2 patches)
        {
            const ull* sT = (const ull*)(bufA + 33792);
            for (int idx = tid; idx < 4096; idx += 512) {
                int cp = idx >> 7, r = idx & 127, i = r >> 4, w = r & 15;
                int pc = w >> 3, j = w & 7;
                ull v = sT[cp * 130 + pc * 64 + i * 8 + j];
                g_t[(((long)(b * 32 + cp)) << 16) + ((ph * 8 + i) << 8) + pw0 * 8 + pc * 8 + j] = v;
            }
        }
        __syncthreads();
    }
}

// ---- kernel 3: passB per 16x16 pixel tile, 512 threads ----------------------
__global__ __launch_bounds__(512, 1) void passB(const float* __restrict__ x,
                                                const float* __restrict__ wdw,
                                                const float* __restrict__ wout,
                                                float* __restrict__ outp) {
    extern __shared__ char sm[];
    ull*   sWo = (ull*)sm;              // [64k][64op] paired 32KB
    float* sDW = (float*)(sm + 32768);  // 576 floats
    ull*   sT  = (ull*)(sm + 35072);    // [32cp][18][18]  82944B
    float* sD  = (float*)(sm + 118016); // [64ch][256px]   64KB

    int tid = threadIdx.x, bx = blockIdx.x;
    int b = bx >> 8, tno = bx & 255;
    int ty = tno >> 4, tx = tno & 15;
    int y0 = ty * 16, x0g = tx * 16;

    // stage wout into sD, pack paired into sWo
    {
        float* st = sD;
        for (int i = tid; i < 8192; i += 512) st[i] = wout[i];
        __syncthreads();
        for (int i = tid; i < 4096; i += 512) {
            int k = i >> 6, op = i & 63;
            sWo[k * 64 + op] = pk2(st[(2 * op) * 64 + k], st[(2 * op + 1) * 64 + k]);
        }
    }
    for (int i = tid; i < 576; i += 512) sDW[i] = wdw[i];
    for (int idx = tid; idx < 10368; idx += 512) {
        int cp = idx / 324, r = idx - cp * 324;
        int ly = r / 18, lx = r - ly * 18;
        int gy = y0 - 1 + ly, gx = x0g - 1 + lx;
        ull v = 0ull;
        if ((unsigned)gy < 256u && (unsigned)gx < 256u)
            v = g_t[(((long)(b * 32 + cp)) << 16) + (gy << 8) + gx];
        sT[idx] = v;
    }
    __syncthreads();

    // depthwise 3x3 (channel pairs) -> sD floats [ch][px]
    {
        int cp = tid >> 4, s = tid & 15, lx0 = (s & 7) * 2, oy0 = (s >> 3) * 8;
        ull w9[9];
#pragma unroll
        for (int t = 0; t < 9; t++)
            w9[t] = pk2(sDW[(2 * cp) * 9 + t], sDW[(2 * cp + 1) * 9 + t]);
        const ull* base = sT + cp * 324;
        for (int oy = oy0; oy < oy0 + 8; ++oy) {
            ull a0 = 0ull, a1 = 0ull;
#pragma unroll
            for (int ki = 0; ki < 3; ki++) {
                const ull* row = base + (oy + ki) * 18 + lx0;
                ull r0 = row[0], r1 = row[1], r2 = row[2], r3 = row[3];
                fma2(a0, w9[ki * 3 + 0], r0);
                fma2(a0, w9[ki * 3 + 1], r1);
                fma2(a0, w9[ki * 3 + 2], r2);
                fma2(a1, w9[ki * 3 + 0], r1);
                fma2(a1, w9[ki * 3 + 1], r2);
                fma2(a1, w9[ki * 3 + 2], r3);
            }
            int px = oy * 16 + lx0;
            sD[(2 * cp) * 256 + px]         = lo32(a0);
            sD[(2 * cp + 1) * 256 + px]     = hi32(a0);
            sD[(2 * cp) * 256 + px + 1]     = lo32(a1);
            sD[(2 * cp + 1) * 256 + px + 1] = hi32(a1);
        }
    }
    __syncthreads();

    // GEMM3 (Wout paired) + residual + store
    {
        int og3 = tid & 15, pg3 = tid >> 4;  // 16 x 32 : 4 opairs x 8 px
        ull acc[4][8];
#pragma unroll
        for (int i = 0; i < 4; i++)
#pragma unroll
            for (int j = 0; j < 8; j++) acc[i][j] = 0ull;
#pragma unroll 4
        for (int k = 0; k < 64; k++) {
            const ull* Ar = sWo + k * 64 + og3;
            ull A0 = Ar[0], A1 = Ar[16], A2 = Ar[32], A3 = Ar[48];
            const float* Br = sD + k * 256 + pg3 * 8;
            float4 b0 = *(const float4*)Br, b1 = *(const float4*)(Br + 4);
            ull B[8] = {pk2(b0.x, b0.x), pk2(b0.y, b0.y), pk2(b0.z, b0.z), pk2(b0.w, b0.w),
                        pk2(b1.x, b1.x), pk2(b1.y, b1.y), pk2(b1.z, b1.z), pk2(b1.w, b1.w)};
#pragma unroll
            for (int j = 0; j < 8; j++) {
                fma2(acc[0][j], A0, B[j]); fma2(acc[1][j], A1, B[j]);
                fma2(acc[2][j], A2, B[j]); fma2(acc[3][j], A3, B[j]);
            }
        }
        int oy = pg3 >> 1, lxb = (pg3 & 1) * 8;
        int gy = y0 + oy, gx = x0g + lxb;
#pragma unroll
        for (int i = 0; i < 4; i++) {
            int ch0 = 2 * (og3 + 16 * i);
            long base0 = (((long)(b * 128 + ch0)) << 16) + (gy << 8) + gx;
            long base1 = base0 + 65536;
            float4 xa0 = *(const float4*)(x + base0), xa1 = *(const float4*)(x + base0 + 4);
            float4 xb0 = *(const float4*)(x + base1), xb1 = *(const float4*)(x + base1 + 4);
            float4 oa0, oa1, ob0, ob1;
            oa0.x = lo32(acc[i][0]) + xa0.x; ob0.x = hi32(acc[i][0]) + xb0.x;
            oa0.y = lo32(acc[i][1]) + xa0.y; ob0.y = hi32(acc[i][1]) + xb0.y;
            oa0.z = lo32(acc[i][2]) + xa0.z; ob0.z = hi32(acc[i][2]) + xb0.z;
            oa0.w = lo32(acc[i][3]) + xa0.w; ob0.w = hi32(acc[i][3]) + xb0.w;
            oa1.x = lo32(acc[i][4]) + xa1.x; ob1.x = hi32(acc[i][4]) + xb1.x;
            oa1.y = lo32(acc[i][5]) + xa1.y; ob1.y = hi32(acc[i][5]) + xb1.y;
            oa1.z = lo32(acc[i][6]) + xa1.z; ob1.z = hi32(acc[i][6]) + xb1.z;
            oa1.w = lo32(acc[i][7]) + xa1.w; ob1.w = hi32(acc[i][7]) + xb1.w;
            *(float4*)(outp + base0)     = oa0;
            *(float4*)(outp + base0 + 4) = oa1;
            *(float4*)(outp + base1)     = ob0;
            *(float4*)(outp + base1 + 4) = ob1;
        }
    }
}

extern "C" void kernel_launch(void* const* d_in, const int* in_sizes, int n_in,
                              void* d_out, int out_size) {
    const float* x        = (const float*)d_in[0];
    const float* fft_filt = (const float*)d_in[1];
    const float* w_in     = (const float*)d_in[2];
    const float* w_before = (const float*)d_in[3];
    const float* w_dw     = (const float*)d_in[4];
    const float* w_out    = (const float*)d_in[5];
    float* outp = (float*)d_out;

    cudaFuncSetAttribute(passA, cudaFuncAttributeMaxDynamicSharedMemorySize, 221184);
    cudaFuncSetAttribute(passB, cudaFuncAttributeMaxDynamicSharedMemorySize, 183552);

    k_build<<<64, 64>>>(fft_filt);
    passA<<<1024, 512, 221184>>>(x, w_in, w_before);
    passB<<<2048, 512, 183552>>>(x, w_dw, w_out, outp);
}

// round 16
// speedup vs baseline: 1.5717x; 1.5717x over previous
#include <cuda_runtime.h>
#include <cuda_bf16.h>

typedef unsigned long long ull;

// scratch (device globals; allocations are forbidden)
__device__ ull g_k[64 * 64];                     // paired circ-conv kernels [cpair][8*8]
__device__ ull g_t[(size_t)8 * 32 * 256 * 256];  // paired intermediate [b][cpair][256][256]

__device__ __forceinline__ ull pk2(float a, float b) {
    ull r; asm("mov.b64 %0, {%1, %2};" : "=l"(r) : "f"(a), "f"(b)); return r;
}
__device__ __forceinline__ void fma2(ull &d, ull a, ull b) {
    asm("fma.rn.f32x2 %0, %1, %2, %0;" : "+l"(d) : "l"(a), "l"(b));
}
__device__ __forceinline__ float lo32(ull v) { return __int_as_float((int)(v & 0xffffffffull)); }
__device__ __forceinline__ float hi32(ull v) { return __int_as_float((int)(v >> 32)); }

// ---- kernel 1: build paired circular-conv kernels from fft_filt -------------
__global__ void k_build(const float* __restrict__ filt) {
    int cp = blockIdx.x, pix = threadIdx.x;
    int di = pix >> 3, dj = pix & 7;
    float v[2];
#pragma unroll
    for (int h = 0; h < 2; h++) {
        const float* F = filt + (cp * 2 + h) * 40;
        float s = 0.f;
        for (int ky = 0; ky < 8; ky++)
            for (int kx = 0; kx < 5; kx++) {
                float w = (kx == 0 || kx == 4) ? 1.f : 2.f;
                int m = (ky * di + kx * dj) & 7;
                s += w * F[ky * 5 + kx] * cospif(0.25f * (float)m);
            }
        v[h] = s * (1.f / 64.f);
    }
    g_k[cp * 64 + pix] = pk2(v[0], v[1]);
}

// ---- kernel 2: passA, 512 threads, 2 patches per iteration ------------------
// smem: sWin(paired)64K | sWb(paired)16K | bufA 68K | bufB 68K  = 221184 B
// bufA: x [128c][132f]  -> g [64c][132f] + t [32cp][130ull]
// bufB: y [64cp][130ull] -> z in place
__global__ __launch_bounds__(512, 1) void passA(const float* __restrict__ x,
                                                const float* __restrict__ w_in,
                                                const float* __restrict__ w_before) {
    extern __shared__ char sm[];
    ull*  sWin = (ull*)sm;                // [128k][64op]
    ull*  sWb  = (ull*)(sm + 65536);      // [64k][32op]
    char* bufA = sm + 81920;              // 69632 B
    char* bufB = sm + 151552;             // 69632 B
    int tid = threadIdx.x;

    // stage + pack weights (paired u64)
    {
        float* stA = (float*)bufA;
        float* stB = (float*)bufB;
        for (int i = tid; i < 16384; i += 512) stA[i] = w_in[i];
        for (int i = tid; i < 4096;  i += 512) stB[i] = w_before[i];
        __syncthreads();
        for (int i = tid; i < 8192; i += 512) {
            int k = i >> 6, op = i & 63;
            sWin[k * 64 + op] = pk2(stA[(2 * op) * 128 + k], stA[(2 * op + 1) * 128 + k]);
        }
        for (int i = tid; i < 2048; i += 512) {
            int k = i >> 5, op = i & 31;
            sWb[k * 32 + op] = pk2(stB[(2 * op) * 64 + k], stB[(2 * op + 1) * 64 + k]);
        }
        __syncthreads();
    }

    const int og  = tid & 15, pg  = tid >> 4;  // GEMM1: 4 opairs x 4 px, pg 0..31
    const int cc  = tid >> 3, sub = tid & 7;   // circconv: cp 0..63, ii=sub, 2 patches
    const int og2 = tid & 7,  pg2 = tid >> 3;  // GEMM2: 4 opairs x 2 px, pg2 0..63

    for (int q = 0; q < 4; ++q) {
        int p2 = blockIdx.x * 4 + q;                       // 0..4095 patch pairs
        int b = p2 >> 9, rem = p2 & 511;
        int ph = rem >> 4, pw0 = (rem & 15) << 1;
        const float* xb = x + ((long)b << 23) + (ph << 11) + (pw0 << 3);

        // load x: [128c][132f] in bufA, px = pc*64 + i*8 + j
        {
            float* sX = (float*)bufA;
            for (int f = tid; f < 4096; f += 512) {
                int c = f >> 5, r = f & 31, i = r >> 2, qq = r & 3;
                float4 v = *(const float4*)(xb + ((long)c << 16) + (i << 8) + (qq << 2));
                int px = (qq < 2) ? (i * 8 + qq * 4) : (64 + i * 8 + (qq - 2) * 4);
                *(float4*)(sX + c * 132 + px) = v;
            }
        }
        __syncthreads();

        // GEMM1: y[64op][128px] paired -> bufB
        {
            const float* sX = (const float*)bufA;
            ull acc[4][4];
#pragma unroll
            for (int i = 0; i < 4; i++)
#pragma unroll
                for (int j = 0; j < 4; j++) acc[i][j] = 0ull;
#pragma unroll 4
            for (int k = 0; k < 128; k++) {
                const ull* Ar = sWin + k * 64 + og;
                ull A0 = Ar[0], A1 = Ar[16], A2 = Ar[32], A3 = Ar[48];
                float4 b0 = *(const float4*)(sX + k * 132 + pg * 4);
                ull B[4] = {pk2(b0.x, b0.x), pk2(b0.y, b0.y), pk2(b0.z, b0.z), pk2(b0.w, b0.w)};
#pragma unroll
                for (int j = 0; j < 4; j++) {
                    fma2(acc[0][j], A0, B[j]); fma2(acc[1][j], A1, B[j]);
                    fma2(acc[2][j], A2, B[j]); fma2(acc[3][j], A3, B[j]);
                }
            }
            ull* sY = (ull*)bufB;
#pragma unroll
            for (int i = 0; i < 4; i++) {
                ull* dst = sY + (og + 16 * i) * 130 + pg * 4;
                ulonglong2 v0; v0.x = acc[i][0]; v0.y = acc[i][1];
                ulonglong2 v1; v1.x = acc[i][2]; v1.y = acc[i][3];
                *(ulonglong2*)(dst)     = v0;
                *(ulonglong2*)(dst + 2) = v1;
            }
        }
        __syncthreads();

        // circular conv 8x8 (K from global L2): z overwrites y in bufB
        {
            ull* sY = (ull*)bufB;
            const ull* kbase = g_k + cc * 64;
            ull z0[8], z1[8];
#pragma unroll
            for (int j = 0; j < 8; j++) { z0[j] = 0; z1[j] = 0; }
#pragma unroll 2
            for (int a = 0; a < 8; a++) {
                const ull* yr = sY + cc * 130 + a * 8;
                ull ya[8], yb[8];
#pragma unroll
                for (int j = 0; j < 8; j += 2) {
                    ulonglong2 v0 = *(const ulonglong2*)(yr + j);      ya[j] = v0.x; ya[j + 1] = v0.y;
                    ulonglong2 v1 = *(const ulonglong2*)(yr + 64 + j); yb[j] = v1.x; yb[j + 1] = v1.y;
                }
                int r1 = (sub - a) & 7;
                ull k1[8];
#pragma unroll
                for (int j = 0; j < 8; j += 2) {
                    ulonglong2 u1 = *(const ulonglong2*)(kbase + r1 * 8 + j);
                    k1[j] = u1.x; k1[j + 1] = u1.y;
                }
#pragma unroll
                for (int j = 0; j < 8; j++)
#pragma unroll
                    for (int bb = 0; bb < 8; bb++) {
                        int r = (j - bb) & 7;
                        fma2(z0[j], ya[bb], k1[r]);
                        fma2(z1[j], yb[bb], k1[r]);
                    }
            }
            __syncwarp();  // all readers of this cc's rows are in this warp
            ull* zr = sY + cc * 130 + sub * 8;
#pragma unroll
            for (int j = 0; j < 8; j += 2) {
                ulonglong2 v;
                v.x = z0[j]; v.y = z0[j + 1]; *(ulonglong2*)(zr + j) = v;
                v.x = z1[j]; v.y = z1[j + 1]; *(ulonglong2*)(zr + 64 + j) = v;
            }
        }
        __syncthreads();

        // exact GELU gate: g floats [64ch][132] -> bufA
        {
            const ull* sZ = (const ull*)bufB;
            float* sG = (float*)bufA;
            for (int idx = tid; idx < 4096; idx += 512) {
                int cp = idx >> 7, u = idx & 127;
                ull za = sZ[cp * 130 + u], zb = sZ[(cp + 32) * 130 + u];
                float a0 = lo32(za), a1 = hi32(za);
                sG[(2 * cp) * 132 + u] =
                    0.5f * a0 * (1.f + erff(a0 * 0.70710678118654752f)) * lo32(zb);
                sG[(2 * cp + 1) * 132 + u] =
                    0.5f * a1 * (1.f + erff(a1 * 0.70710678118654752f)) * hi32(zb);
            }
        }
        __syncthreads();

        // GEMM2: t[32op][128px] paired -> bufA+33792 (all 512 threads)
        {
            const float* sG = (const float*)bufA;
            ull acc[4][2];
#pragma unroll
            for (int i = 0; i < 4; i++) { acc[i][0] = 0ull; acc[i][1] = 0ull; }
#pragma unroll 4
            for (int k = 0; k < 64; k++) {
                const ull* Ar = sWb + k * 32 + og2;
                ull A0 = Ar[0], A1 = Ar[8], A2 = Ar[16], A3 = Ar[24];
                float2 gg = *(const float2*)(sG + k * 132 + pg2 * 2);
                ull b0 = pk2(gg.x, gg.x), b1 = pk2(gg.y, gg.y);
                fma2(acc[0][0], A0, b0); fma2(acc[0][1], A0, b1);
                fma2(acc[1][0], A1, b0); fma2(acc[1][1], A1, b1);
                fma2(acc[2][0], A2, b0); fma2(acc[2][1], A2, b1);
                fma2(acc[3][0], A3, b0); fma2(acc[3][1], A3, b1);
            }
            ull* sT = (ull*)(bufA + 33792);
#pragma unroll
            for (int i = 0; i < 4; i++) {
                ulonglong2 v; v.x = acc[i][0]; v.y = acc[i][1];
                *(ulonglong2*)(sT + (og2 + 8 * i) * 130 + pg2 * 2) = v;
            }
        }
        __syncthreads();

        // store paired t to global (128B-contiguous across the 2 patches)
        {
            const ull* sT = (const ull*)(bufA + 33792);
            for (int idx = tid; idx < 4096; idx += 512) {
                int cp = idx >> 7, r = idx & 127, i = r >> 4, w = r & 15;
                int pc = w >> 3, j = w & 7;
                ull v = sT[cp * 130 + pc * 64 + i * 8 + j];
                g_t[(((long)(b * 32 + cp)) << 16) + ((ph * 8 + i) << 8) + pw0 * 8 + pc * 8 + j] = v;
            }
        }
        __syncthreads();
    }
}

// ---- kernel 3: passB per 16x16 pixel tile, 512 threads ----------------------
__global__ __launch_bounds__(512, 1) void passB(const float* __restrict__ x,
                                                const float* __restrict__ wdw,
                                                const float* __restrict__ wout,
                                                float* __restrict__ outp) {
    extern __shared__ char sm[];
    ull*   sWo = (ull*)sm;              // [64k][64op] paired 32KB
    float* sDW = (float*)(sm + 32768);  // 576 floats
    ull*   sT  = (ull*)(sm + 35072);    // [32cp][18][18]  82944B
    float* sD  = (float*)(sm + 118016); // [64ch][256px]   64KB

    int tid = threadIdx.x, bx = blockIdx.x;
    int b = bx >> 8, tno = bx & 255;
    int ty = tno >> 4, tx = tno & 15;
    int y0 = ty * 16, x0g = tx * 16;

    // stage wout into sD, pack paired into sWo
    {
        float* st = sD;
        for (int i = tid; i < 8192; i += 512) st[i] = wout[i];
        __syncthreads();
        for (int i = tid; i < 4096; i += 512) {
            int k = i >> 6, op = i & 63;
            sWo[k * 64 + op] = pk2(st[(2 * op) * 64 + k], st[(2 * op + 1) * 64 + k]);
        }
    }
    for (int i = tid; i < 576; i += 512) sDW[i] = wdw[i];
    for (int idx = tid; idx < 10368; idx += 512) {
        int cp = idx / 324, r = idx - cp * 324;
        int ly = r / 18, lx = r - ly * 18;
        int gy = y0 - 1 + ly, gx = x0g - 1 + lx;
        ull v = 0ull;
        if ((unsigned)gy < 256u && (unsigned)gx < 256u)
            v = g_t[(((long)(b * 32 + cp)) << 16) + (gy << 8) + gx];
        sT[idx] = v;
    }
    __syncthreads();

    // depthwise 3x3 (channel pairs) -> sD floats [ch][px]
    {
        int cp = tid >> 4, s = tid & 15, lx0 = (s & 7) * 2, oy0 = (s >> 3) * 8;
        ull w9[9];
#pragma unroll
        for (int t = 0; t < 9; t++)
            w9[t] = pk2(sDW[(2 * cp) * 9 + t], sDW[(2 * cp + 1) * 9 + t]);
        const ull* base = sT + cp * 324;
        for (int oy = oy0; oy < oy0 + 8; ++oy) {
            ull a0 = 0ull, a1 = 0ull;
#pragma unroll
            for (int ki = 0; ki < 3; ki++) {
                const ull* row = base + (oy + ki) * 18 + lx0;
                ull r0 = row[0], r1 = row[1], r2 = row[2], r3 = row[3];
                fma2(a0, w9[ki * 3 + 0], r0);
                fma2(a0, w9[ki * 3 + 1], r1);
                fma2(a0, w9[ki * 3 + 2], r2);
                fma2(a1, w9[ki * 3 + 0], r1);
                fma2(a1, w9[ki * 3 + 1], r2);
                fma2(a1, w9[ki * 3 + 2], r3);
            }
            int px = oy * 16 + lx0;
            sD[(2 * cp) * 256 + px]         = lo32(a0);
            sD[(2 * cp + 1) * 256 + px]     = hi32(a0);
            sD[(2 * cp) * 256 + px + 1]     = lo32(a1);
            sD[(2 * cp + 1) * 256 + px + 1] = hi32(a1);
        }
    }
    __syncthreads();

    // GEMM3 (Wout paired) + residual + store
    {
        int og3 = tid & 15, pg3 = tid >> 4;  // 16 x 32 : 4 opairs x 8 px
        ull acc[4][8];
#pragma unroll
        for (int i = 0; i < 4; i++)
#pragma unroll
            for (int j = 0; j < 8; j++) acc[i][j] = 0ull;
#pragma unroll 4
        for (int k = 0; k < 64; k++) {
            const ull* Ar = sWo + k * 64 + og3;
            ull A0 = Ar[0], A1 = Ar[16], A2 = Ar[32], A3 = Ar[48];
            const float* Br = sD + k * 256 + pg3 * 8;
            float4 b0 = *(const float4*)Br, b1 = *(const float4*)(Br + 4);
            ull B[8] = {pk2(b0.x, b0.x), pk2(b0.y, b0.y), pk2(b0.z, b0.z), pk2(b0.w, b0.w),
                        pk2(b1.x, b1.x), pk2(b1.y, b1.y), pk2(b1.z, b1.z), pk2(b1.w, b1.w)};
#pragma unroll
            for (int j = 0; j < 8; j++) {
                fma2(acc[0][j], A0, B[j]); fma2(acc[1][j], A1, B[j]);
                fma2(acc[2][j], A2, B[j]); fma2(acc[3][j], A3, B[j]);
            }
        }
        int oy = pg3 >> 1, lxb = (pg3 & 1) * 8;
        int gy = y0 + oy, gx = x0g + lxb;
#pragma unroll
        for (int i = 0; i < 4; i++) {
            int ch0 = 2 * (og3 + 16 * i);
            long base0 = (((long)(b * 128 + ch0)) << 16) + (gy << 8) + gx;
            long base1 = base0 + 65536;
            float4 xa0 = *(const float4*)(x + base0), xa1 = *(const float4*)(x + base0 + 4);
            float4 xb0 = *(const float4*)(x + base1), xb1 = *(const float4*)(x + base1 + 4);
            float4 oa0, oa1, ob0, ob1;
            oa0.x = lo32(acc[i][0]) + xa0.x; ob0.x = hi32(acc[i][0]) + xb0.x;
            oa0.y = lo32(acc[i][1]) + xa0.y; ob0.y = hi32(acc[i][1]) + xb0.y;
            oa0.z = lo32(acc[i][2]) + xa0.z; ob0.z = hi32(acc[i][2]) + xb0.z;
            oa0.w = lo32(acc[i][3]) + xa0.w; ob0.w = hi32(acc[i][3]) + xb0.w;
            oa1.x = lo32(acc[i][4]) + xa1.x; ob1.x = hi32(acc[i][4]) + xb1.x;
            oa1.y = lo32(acc[i][5]) + xa1.y; ob1.y = hi32(acc[i][5]) + xb1.y;
            oa1.z = lo32(acc[i][6]) + xa1.z; ob1.z = hi32(acc[i][6]) + xb1.z;
            oa1.w = lo32(acc[i][7]) + xa1.w; ob1.w = hi32(acc[i][7]) + xb1.w;
            *(float4*)(outp + base0)     = oa0;
            *(float4*)(outp + base0 + 4) = oa1;
            *(float4*)(outp + base1)     = ob0;
            *(float4*)(outp + base1 + 4) = ob1;
        }
    }
}

extern "C" void kernel_launch(void* const* d_in, const int* in_sizes, int n_in,
                              void* d_out, int out_size) {
    const float* x        = (const float*)d_in[0];
    const float* fft_filt = (const float*)d_in[1];
    const float* w_in     = (const float*)d_in[2];
    const float* w_before = (const float*)d_in[3];
    const float* w_dw     = (const float*)d_in[4];
    const float* w_out    = (const float*)d_in[5];
    float* outp = (float*)d_out;

    cudaFuncSetAttribute(passA, cudaFuncAttributeMaxDynamicSharedMemorySize, 221184);
    cudaFuncSetAttribute(passB, cudaFuncAttributeMaxDynamicSharedMemorySize, 183552);

    k_build<<<64, 64>>>(fft_filt);
    passA<<<1024, 512, 221184>>>(x, w_in, w_before);
    passB<<<2048, 512, 183552>>>(x, w_dw, w_out, outp);
}